// round 12
// baseline (speedup 1.0000x reference)
#include <cuda_runtime.h>
#include <cuda_fp16.h>
#include <math.h>

// EpochedFutureFill: y[b,t] = sum_s filt[s] * x[b,t-s] via 65536-pt FFT conv.
// 65536 = 256 x 256 four-step; row pairs packed as complex; fp16 scratch.
// Chunked (64 pairs) so each chunk's 8MB scratch slice stays L2-resident
// across its P1->P2->P3 sequence; PDL overlaps next-chunk P1 with P3.
// Chunk layout: addr(k1,j2) = pr*65536 + (k1>>4)*4096 + (j2>>4)*256
//               + (k1&15)*16 + (j2&15)  -> offset == tid everywhere.

#define T_LEN 32768
#define NFFT  65536
#define NPAIRS 128
#define CH 64
#define PI_F 3.14159265358979323846f

__device__ __half2 g_Gh[(size_t)NPAIRS * NFFT]; // 32MB scratch (P2 in-place)
__device__ float2  g_Gf[NFFT];                  // filter intermediate (fp32)
__device__ float2  g_Wp[NFFT];                  // filter spectrum (fp32)

__device__ __forceinline__ void pdl_wait(){
    asm volatile("griddepcontrol.wait;" ::: "memory");
}
__device__ __forceinline__ void pdl_launch_dependents(){
    asm volatile("griddepcontrol.launch_dependents;" ::: "memory");
}

__device__ __forceinline__ float2 cmul(float2 a, float2 b) {
    return make_float2(a.x*b.x - a.y*b.y, a.x*b.y + a.y*b.x);
}
__device__ __forceinline__ float2 cadd(float2 a, float2 b){ return make_float2(a.x+b.x, a.y+b.y); }
__device__ __forceinline__ float2 csub(float2 a, float2 b){ return make_float2(a.x-b.x, a.y-b.y); }

// base-4 digit swap (involution); fft16 leaves output index PERM(s) in slot s.
#define PERM(s) ((((s)&3)<<2) | ((s)>>2))
__device__ __forceinline__ constexpr int pm(int i, bool P){
    return P ? (((i & 3) << 2) | (i >> 2)) : i;
}

template<int SIGN>
__device__ __forceinline__ void bf4(float2&a, float2&b, float2&c, float2&d){
    float2 apc = cadd(a,c), amc = csub(a,c);
    float2 bpd = cadd(b,d), bmd = csub(b,d);
    float2 y1, y3;
    if (SIGN < 0){
        y1 = make_float2(amc.x + bmd.y, amc.y - bmd.x);
        y3 = make_float2(amc.x - bmd.y, amc.y + bmd.x);
    } else {
        y1 = make_float2(amc.x - bmd.y, amc.y + bmd.x);
        y3 = make_float2(amc.x + bmd.y, amc.y - bmd.x);
    }
    a = cadd(apc, bpd); b = y1; c = csub(apc, bpd); d = y3;
}

template<int SIGN>
__device__ __forceinline__ float2 mulw(float2 a, float cr, float si){
    float wi = (SIGN < 0) ? -si : si;
    return make_float2(a.x*cr - a.y*wi, a.x*wi + a.y*cr);
}

// fft16 over a (possibly PERM-permuted) register view.
template<int SIGN, bool P>
__device__ __forceinline__ void fft16m(float2 v[16]){
    bf4<SIGN>(v[pm(0,P)], v[pm(4,P)], v[pm(8,P)],  v[pm(12,P)]);
    bf4<SIGN>(v[pm(1,P)], v[pm(5,P)], v[pm(9,P)],  v[pm(13,P)]);
    bf4<SIGN>(v[pm(2,P)], v[pm(6,P)], v[pm(10,P)], v[pm(14,P)]);
    bf4<SIGN>(v[pm(3,P)], v[pm(7,P)], v[pm(11,P)], v[pm(15,P)]);
    const float C1 = 0.923879532511287f, S1 = 0.382683432365090f, C2 = 0.707106781186548f;
    v[pm(5,P)]  = mulw<SIGN>(v[pm(5,P)],  C1,  S1);
    v[pm(9,P)]  = mulw<SIGN>(v[pm(9,P)],  C2,  C2);
    v[pm(13,P)] = mulw<SIGN>(v[pm(13,P)], S1,  C1);
    v[pm(6,P)]  = mulw<SIGN>(v[pm(6,P)],  C2,  C2);
    v[pm(10,P)] = (SIGN<0) ? make_float2(v[pm(10,P)].y, -v[pm(10,P)].x)
                           : make_float2(-v[pm(10,P)].y, v[pm(10,P)].x);
    v[pm(14,P)] = mulw<SIGN>(v[pm(14,P)], -C2, C2);
    v[pm(7,P)]  = mulw<SIGN>(v[pm(7,P)],  S1,  C1);
    v[pm(11,P)] = mulw<SIGN>(v[pm(11,P)], -C2, C2);
    v[pm(15,P)] = mulw<SIGN>(v[pm(15,P)], -C1, -S1);
    bf4<SIGN>(v[pm(0,P)],  v[pm(1,P)],  v[pm(2,P)],  v[pm(3,P)]);
    bf4<SIGN>(v[pm(4,P)],  v[pm(5,P)],  v[pm(6,P)],  v[pm(7,P)]);
    bf4<SIGN>(v[pm(8,P)],  v[pm(9,P)],  v[pm(10,P)], v[pm(11,P)]);
    bf4<SIGN>(v[pm(12,P)], v[pm(13,P)], v[pm(14,P)], v[pm(15,P)]);
}

// Transpose smem addressing. LAYB=false: roles (col=tid&15, r=tid>>4), pad-17.
// LAYB=true: roles (col=tid>>4, r=tid&15), XOR-swizzled (bank-clean for both).
template<bool LAYB>
__device__ __forceinline__ int taddr(int p, int col){
    return LAYB ? (col*272 + (p ^ (p>>4))) : (p*17 + col);
}

// 256-pt FFT. Input: logical slot i holds f[16*i + r] — physically v[i]
// (INPERM=false) or v[PERM(i)] (INPERM=true). Output: X[r+16*k2] in v[PERM(k2)].
// One smem transpose; two-chain twiddles.
template<int SIGN, bool PRESYNC, bool LAYB, bool INPERM>
__device__ __forceinline__ void fft256_reg(float2 v[16], float2* buf, int col, int r){
    fft16m<SIGN, INPERM>(v);
    float s0, c0;
    sincosf((float)SIGN * (2.0f*PI_F/256.0f) * (float)r, &s0, &c0);
    float2 stp  = make_float2(c0, s0);
    float2 stp2 = cmul(stp, stp);
    float2 fe = make_float2(1.f, 0.f), fo = stp;
    if (PRESYNC) __syncthreads();
#pragma unroll
    for (int k1 = 0; k1 < 16; ++k1){
        float2 t = (k1 & 1) ? cmul(v[pm(PERM(k1), INPERM)], fo)
                            : cmul(v[pm(PERM(k1), INPERM)], fe);
        buf[taddr<LAYB>(k1*16 + r, col)] = t;
        if (k1 & 1) fo = cmul(fo, stp2); else fe = cmul(fe, stp2);
    }
    __syncthreads();
#pragma unroll
    for (int n2 = 0; n2 < 16; ++n2)
        v[n2] = buf[taddr<LAYB>(r*16 + n2, col)];
    fft16m<SIGN, false>(v);
}

// ------- Pass 1: forward column FFTs + outer twiddle; y==filt_row: filter -----
// Reads only x/flt (graph inputs): needs NO griddepcontrol.wait -> can overlap
// the previous chunk's P3 entirely.
__global__ void __launch_bounds__(256, 5) k_fwd_cols(const float* __restrict__ x,
                                                     const float* __restrict__ flt,
                                                     int pr_base, int filt_row){
    __shared__ float2 buf[4352];
    const int tid = threadIdx.x, col = tid & 15, r = tid >> 4;
    const int tile = blockIdx.x;
    const int j2 = tile*16 + col;
    const bool isf = ((int)blockIdx.y == filt_row);
    const int pr = pr_base + (int)blockIdx.y;
    const float* x0 = isf ? flt : (x + (size_t)(2*pr)*T_LEN);
    const float* x1 = x0 + T_LEN;
    float2 v[16];
#pragma unroll
    for (int n1 = 0; n1 < 16; ++n1){
        if (n1 < 8){
            int j = (16*n1 + r)*256 + j2;
            float re = __ldcs(x0 + j);
            float im = isf ? 0.f : __ldcs(x1 + j);
            v[n1] = make_float2(re, im);
        } else v[n1] = make_float2(0.f, 0.f);
    }
    fft256_reg<-1,false,false,false>(v, buf, col, r);
    float s0,c0,s1,c1;
    sincosf(-(2.0f*PI_F/65536.0f)*(float)(j2*r),  &s0,&c0);
    sincosf(-(2.0f*PI_F/65536.0f)*(float)(j2*32), &s1,&c1);
    float2 f0 = make_float2(c0,s0), stp2 = make_float2(c1,s1);
    sincosf(-(2.0f*PI_F/65536.0f)*(float)(j2*16), &s1,&c1);
    float2 f1 = cmul(f0, make_float2(c1,s1));
    if (isf){
#pragma unroll
        for (int k2 = 0; k2 < 16; ++k2){
            float2 t = (k2 & 1) ? cmul(v[PERM(k2)], f1) : cmul(v[PERM(k2)], f0);
            g_Gf[k2*4096 + tile*256 + tid] = t;
            if (k2 & 1) f1 = cmul(f1, stp2); else f0 = cmul(f0, stp2);
        }
    } else {
        __half2* g = g_Gh + (size_t)pr*NFFT;
#pragma unroll
        for (int k2 = 0; k2 < 16; ++k2){
            // k1 = r + 16*k2 -> chunk (k2, tile), offset tid
            float2 t = (k2 & 1) ? cmul(v[PERM(k2)], f1) : cmul(v[PERM(k2)], f0);
            g[k2*4096 + tile*256 + tid] = __floats2half2_rn(t.x, t.y);
            if (k2 & 1) f1 = cmul(f1, stp2); else f0 = cmul(f0, stp2);
        }
    }
}

// ----------- Filter pass 2: row FFTs -> spectrum in chunk layout (shfl) -------
template<int SIGN, bool INPERM>
__device__ __forceinline__ void fft256_shfl(float2 v[16], int r){
    fft16m<SIGN, INPERM>(v);
    float s0, c0;
    sincosf((float)SIGN * (2.0f*PI_F/256.0f) * (float)r, &s0, &c0);
    float2 stp  = make_float2(c0, s0);
    float2 stp2 = cmul(stp, stp);
    float2 fe = make_float2(1.f, 0.f), fo = stp;
    float2 w[16];
#pragma unroll
    for (int k1 = 0; k1 < 16; ++k1){
        w[k1] = (k1 & 1) ? cmul(v[pm(PERM(k1), INPERM)], fo)
                         : cmul(v[pm(PERM(k1), INPERM)], fe);
        if (k1 & 1) fo = cmul(fo, stp2); else fe = cmul(fe, stp2);
    }
#pragma unroll
    for (int m = 1; m < 16; m <<= 1){
        const bool flip = (r & m) != 0;
#pragma unroll
        for (int i = 0; i < 16; ++i){
            if (i & m) continue;
            const int j = i | m;
            float2 send = flip ? w[i] : w[j];
            float2 recv;
            recv.x = __shfl_xor_sync(0xffffffffu, send.x, m);
            recv.y = __shfl_xor_sync(0xffffffffu, send.y, m);
            if (flip) w[i] = recv; else w[j] = recv;
        }
    }
    fft16m<SIGN, false>(w);
#pragma unroll
    for (int i = 0; i < 16; ++i) v[i] = w[i];
}

__global__ void __launch_bounds__(256) k_rows_filt(){
    const int tid = threadIdx.x, r = tid & 15;
    const int tile = blockIdx.x;
    pdl_wait();                                  // g_Gf from chunk-0 P1
    float2 v[16];
#pragma unroll
    for (int i = 0; i < 16; ++i)
        v[i] = g_Gf[tile*4096 + i*256 + tid];
    fft256_shfl<-1,false>(v, r);
#pragma unroll
    for (int k2 = 0; k2 < 16; ++k2)
        g_Wp[tile*4096 + k2*256 + tid] = v[PERM(k2)];
}

// ------ Pass 2: finish forward, multiply W, start inverse (in place) ----------
__global__ void __launch_bounds__(256, 4) k_rows_conv(int pr_base){
    __shared__ float2 buf[4352];
    const int tid = threadIdx.x, col = tid >> 4, r = tid & 15;   // swapped roles
    const int tile = blockIdx.x;
    __half2* g = g_Gh + (size_t)(pr_base + (int)blockIdx.y) * NFFT;
    pdl_wait();                                  // predecessor's g / W writes
    float2 v[16];
#pragma unroll
    for (int i = 0; i < 16; ++i)
        v[i] = __half22float2(__ldcs(&g[tile*4096 + i*256 + tid]));  // last read
    fft256_reg<-1,false,true,false>(v, buf, col, r);  // Z[row][r+16k2] in v[PERM(k2)]
    // multiply by W in place; logical inverse-input slot k2 lives at v[PERM(k2)]
#pragma unroll
    for (int k2 = 0; k2 < 16; ++k2){
        float2 w = g_Wp[tile*4096 + k2*256 + tid];
        v[PERM(k2)] = cmul(v[PERM(k2)], w);
    }
    fft256_reg<1,true,true,true>(v, buf, col, r);     // D[jj=r+16b] in v[PERM(b)]
    // inverse outer twiddle exp(+2pi i*k1row*jj/65536) with 1/N folded in
    const int k1row = tile*16 + col;
    const float sc = 1.0f / (float)NFFT;
    float s0,c0,s1,c1;
    sincosf((2.0f*PI_F/65536.0f)*(float)(k1row*r),  &s0,&c0);
    sincosf((2.0f*PI_F/65536.0f)*(float)(k1row*32), &s1,&c1);
    float2 f0 = make_float2(c0*sc, s0*sc), stp2 = make_float2(c1,s1);
    sincosf((2.0f*PI_F/65536.0f)*(float)(k1row*16), &s1,&c1);
    float2 f1 = cmul(f0, make_float2(c1,s1));
#pragma unroll
    for (int b = 0; b < 16; ++b){
        float2 t = (b & 1) ? cmul(v[PERM(b)], f1) : cmul(v[PERM(b)], f0);
        g[tile*4096 + b*256 + tid] = __floats2half2_rn(t.x, t.y);
        if (b & 1) f1 = cmul(f1, stp2); else f0 = cmul(f0, stp2);
    }
}

// ---------------- Pass 3: inverse column FFTs + output ------------------------
// Triggers dependents at ENTRY: nothing downstream reads y, so the next
// chunk's P1 (which needs no wait) can run fully concurrent with this kernel.
__global__ void __launch_bounds__(256, 5) k_inv_cols(float* __restrict__ y, int pr_base){
    pdl_launch_dependents();
    __shared__ float2 buf[4352];
    const int tid = threadIdx.x, col = tid & 15, r = tid >> 4;
    const int tile = blockIdx.x, pr = pr_base + (int)blockIdx.y;
    const int j1 = tile*16 + col;
    const __half2* g = g_Gh + (size_t)pr * NFFT;
    pdl_wait();                                  // P2's g writes
    float2 v[16];
#pragma unroll
    for (int n1 = 0; n1 < 16; ++n1)
        v[n1] = __half22float2(__ldcs(&g[n1*4096 + tile*256 + tid]));  // last read
    fft256_reg<1,false,false,false>(v, buf, col, r);
    float* y0 = y + (size_t)(2*pr)*T_LEN;
    float* y1 = y0 + T_LEN;
#pragma unroll
    for (int k2 = 0; k2 < 8; ++k2){             // j2o = r+16*k2 < 128 only
        int j2o = r + 16*k2;
        float2 t = v[PERM(k2)];                 // 1/N already applied in P2
        int j = j2o*256 + j1;
        __stcs(y0 + j, t.x);
        __stcs(y1 + j, t.y);
    }
}

extern "C" void kernel_launch(void* const* d_in, const int* in_sizes, int n_in,
                              void* d_out, int out_size) {
    const float* x   = (const float*)d_in[0];
    const float* flt = (const float*)d_in[1];
    float* y = (float*)d_out;
    int B = in_sizes[0] / T_LEN;     // 256
    int npairs = B / 2;              // 128
    int nchunks = (npairs + CH - 1) / CH;

    cudaLaunchAttribute at;
    at.id = cudaLaunchAttributeProgrammaticStreamSerialization;
    at.val.programmaticStreamSerializationAllowed = 1;

    cudaLaunchConfig_t cfg;
    memset(&cfg, 0, sizeof(cfg));
    cfg.blockDim = dim3(256, 1, 1);
    cfg.stream = 0;

    bool firstLaunch = true;
    for (int c = 0; c < nchunks; ++c){
        int base = c * CH;
        int nc = (npairs - base < CH) ? (npairs - base) : CH;
        bool first = (c == 0);

        // P1 (chunk 0 carries the filter row as an extra blockIdx.y)
        cfg.gridDim = dim3(16, nc + (first ? 1 : 0), 1);
        cfg.attrs = firstLaunch ? nullptr : &at;
        cfg.numAttrs = firstLaunch ? 0 : 1;
        cudaLaunchKernelEx(&cfg, k_fwd_cols, x, flt, base, first ? nc : -1);
        firstLaunch = false;

        if (first){
            cfg.gridDim = dim3(16, 1, 1);
            cfg.attrs = &at; cfg.numAttrs = 1;
            cudaLaunchKernelEx(&cfg, k_rows_filt);
        }

        cfg.gridDim = dim3(16, nc, 1);
        cfg.attrs = &at; cfg.numAttrs = 1;
        cudaLaunchKernelEx(&cfg, k_rows_conv, base);

        cfg.gridDim = dim3(16, nc, 1);
        cfg.attrs = &at; cfg.numAttrs = 1;
        cudaLaunchKernelEx(&cfg, k_inv_cols, y, base);
    }
}

// round 13
// speedup vs baseline: 1.6547x; 1.6547x over previous
#include <cuda_runtime.h>
#include <cuda_fp16.h>
#include <math.h>
#include <string.h>

// EpochedFutureFill: y[b,t] = sum_s filt[s] * x[b,t-s] via 65536-pt FFT conv.
// 65536 = 256 x 256 four-step; row pairs packed as complex; fp16 scratch
// (halves the dominant DRAM stream; 1/N folded into P2's output twiddle).
// Monolithic full-width launches (chunking failed twice: wave quantization),
// stitched with PDL so each grid's ramp overlaps the predecessor's drain.
// Chunk layout: addr(k1,j2) = pr*65536 + (k1>>4)*4096 + (j2>>4)*256
//               + (k1&15)*16 + (j2&15)  -> offset == tid everywhere.

#define T_LEN 32768
#define NFFT  65536
#define NPAIRS 128
#define PI_F 3.14159265358979323846f

__device__ __half2 g_Gh[(size_t)NPAIRS * NFFT]; // 32MB scratch (P2 in-place)
__device__ float2  g_Gf[NFFT];                  // filter intermediate (fp32)
__device__ float2  g_Wp[NFFT];                  // filter spectrum (fp32)

__device__ __forceinline__ void pdl_wait(){
    asm volatile("griddepcontrol.wait;" ::: "memory");
}

__device__ __forceinline__ float2 cmul(float2 a, float2 b) {
    return make_float2(a.x*b.x - a.y*b.y, a.x*b.y + a.y*b.x);
}
__device__ __forceinline__ float2 cadd(float2 a, float2 b){ return make_float2(a.x+b.x, a.y+b.y); }
__device__ __forceinline__ float2 csub(float2 a, float2 b){ return make_float2(a.x-b.x, a.y-b.y); }

// base-4 digit swap (involution); fft16 leaves output index PERM(s) in slot s.
#define PERM(s) ((((s)&3)<<2) | ((s)>>2))
__device__ __forceinline__ constexpr int pm(int i, bool P){
    return P ? (((i & 3) << 2) | (i >> 2)) : i;
}

template<int SIGN>
__device__ __forceinline__ void bf4(float2&a, float2&b, float2&c, float2&d){
    float2 apc = cadd(a,c), amc = csub(a,c);
    float2 bpd = cadd(b,d), bmd = csub(b,d);
    float2 y1, y3;
    if (SIGN < 0){
        y1 = make_float2(amc.x + bmd.y, amc.y - bmd.x);
        y3 = make_float2(amc.x - bmd.y, amc.y + bmd.x);
    } else {
        y1 = make_float2(amc.x - bmd.y, amc.y + bmd.x);
        y3 = make_float2(amc.x + bmd.y, amc.y - bmd.x);
    }
    a = cadd(apc, bpd); b = y1; c = csub(apc, bpd); d = y3;
}

template<int SIGN>
__device__ __forceinline__ float2 mulw(float2 a, float cr, float si){
    float wi = (SIGN < 0) ? -si : si;
    return make_float2(a.x*cr - a.y*wi, a.x*wi + a.y*cr);
}

// fft16 over a (possibly PERM-permuted) register view.
template<int SIGN, bool P>
__device__ __forceinline__ void fft16m(float2 v[16]){
    bf4<SIGN>(v[pm(0,P)], v[pm(4,P)], v[pm(8,P)],  v[pm(12,P)]);
    bf4<SIGN>(v[pm(1,P)], v[pm(5,P)], v[pm(9,P)],  v[pm(13,P)]);
    bf4<SIGN>(v[pm(2,P)], v[pm(6,P)], v[pm(10,P)], v[pm(14,P)]);
    bf4<SIGN>(v[pm(3,P)], v[pm(7,P)], v[pm(11,P)], v[pm(15,P)]);
    const float C1 = 0.923879532511287f, S1 = 0.382683432365090f, C2 = 0.707106781186548f;
    v[pm(5,P)]  = mulw<SIGN>(v[pm(5,P)],  C1,  S1);
    v[pm(9,P)]  = mulw<SIGN>(v[pm(9,P)],  C2,  C2);
    v[pm(13,P)] = mulw<SIGN>(v[pm(13,P)], S1,  C1);
    v[pm(6,P)]  = mulw<SIGN>(v[pm(6,P)],  C2,  C2);
    v[pm(10,P)] = (SIGN<0) ? make_float2(v[pm(10,P)].y, -v[pm(10,P)].x)
                           : make_float2(-v[pm(10,P)].y, v[pm(10,P)].x);
    v[pm(14,P)] = mulw<SIGN>(v[pm(14,P)], -C2, C2);
    v[pm(7,P)]  = mulw<SIGN>(v[pm(7,P)],  S1,  C1);
    v[pm(11,P)] = mulw<SIGN>(v[pm(11,P)], -C2, C2);
    v[pm(15,P)] = mulw<SIGN>(v[pm(15,P)], -C1, -S1);
    bf4<SIGN>(v[pm(0,P)],  v[pm(1,P)],  v[pm(2,P)],  v[pm(3,P)]);
    bf4<SIGN>(v[pm(4,P)],  v[pm(5,P)],  v[pm(6,P)],  v[pm(7,P)]);
    bf4<SIGN>(v[pm(8,P)],  v[pm(9,P)],  v[pm(10,P)], v[pm(11,P)]);
    bf4<SIGN>(v[pm(12,P)], v[pm(13,P)], v[pm(14,P)], v[pm(15,P)]);
}

// Transpose smem addressing. LAYB=false: roles (col=tid&15, r=tid>>4), pad-17.
// LAYB=true: roles (col=tid>>4, r=tid&15), XOR-swizzled (bank-clean for both).
template<bool LAYB>
__device__ __forceinline__ int taddr(int p, int col){
    return LAYB ? (col*272 + (p ^ (p>>4))) : (p*17 + col);
}

// 256-pt FFT. Input: logical slot i holds f[16*i + r] — physically v[i]
// (INPERM=false) or v[PERM(i)] (INPERM=true). Output: X[r+16*k2] in v[PERM(k2)].
// One smem transpose; two-chain twiddles.
template<int SIGN, bool PRESYNC, bool LAYB, bool INPERM>
__device__ __forceinline__ void fft256_reg(float2 v[16], float2* buf, int col, int r){
    fft16m<SIGN, INPERM>(v);
    float s0, c0;
    sincosf((float)SIGN * (2.0f*PI_F/256.0f) * (float)r, &s0, &c0);
    float2 stp  = make_float2(c0, s0);
    float2 stp2 = cmul(stp, stp);
    float2 fe = make_float2(1.f, 0.f), fo = stp;
    if (PRESYNC) __syncthreads();
#pragma unroll
    for (int k1 = 0; k1 < 16; ++k1){
        float2 t = (k1 & 1) ? cmul(v[pm(PERM(k1), INPERM)], fo)
                            : cmul(v[pm(PERM(k1), INPERM)], fe);
        buf[taddr<LAYB>(k1*16 + r, col)] = t;
        if (k1 & 1) fo = cmul(fo, stp2); else fe = cmul(fe, stp2);
    }
    __syncthreads();
#pragma unroll
    for (int n2 = 0; n2 < 16; ++n2)
        v[n2] = buf[taddr<LAYB>(r*16 + n2, col)];
    fft16m<SIGN, false>(v);
}

// ------- Pass 1 (fused): forward column FFTs + outer twiddle; y==128: filter --
// Reads only graph inputs (x, flt): no pdl_wait needed.
__global__ void __launch_bounds__(256, 5) k_fwd_cols(const float* __restrict__ x,
                                                     const float* __restrict__ flt){
    __shared__ float2 buf[4352];
    const int tid = threadIdx.x, col = tid & 15, r = tid >> 4;
    const int tile = blockIdx.x, pr = blockIdx.y;
    const int j2 = tile*16 + col;
    const bool isf = (pr == NPAIRS);
    const float* x0 = isf ? flt : (x + (size_t)(2*pr)*T_LEN);
    const float* x1 = x0 + T_LEN;
    float2 v[16];
#pragma unroll
    for (int n1 = 0; n1 < 16; ++n1){
        if (n1 < 8){
            int j = (16*n1 + r)*256 + j2;
            float re = __ldcs(x0 + j);
            float im = isf ? 0.f : __ldcs(x1 + j);
            v[n1] = make_float2(re, im);
        } else v[n1] = make_float2(0.f, 0.f);
    }
    fft256_reg<-1,false,false,false>(v, buf, col, r);
    float s0,c0,s1,c1;
    sincosf(-(2.0f*PI_F/65536.0f)*(float)(j2*r),  &s0,&c0);
    sincosf(-(2.0f*PI_F/65536.0f)*(float)(j2*32), &s1,&c1);
    float2 f0 = make_float2(c0,s0), stp2 = make_float2(c1,s1);
    sincosf(-(2.0f*PI_F/65536.0f)*(float)(j2*16), &s1,&c1);
    float2 f1 = cmul(f0, make_float2(c1,s1));
    if (isf){
#pragma unroll
        for (int k2 = 0; k2 < 16; ++k2){
            float2 t = (k2 & 1) ? cmul(v[PERM(k2)], f1) : cmul(v[PERM(k2)], f0);
            g_Gf[k2*4096 + tile*256 + tid] = t;
            if (k2 & 1) f1 = cmul(f1, stp2); else f0 = cmul(f0, stp2);
        }
    } else {
        __half2* g = g_Gh + (size_t)pr*NFFT;
#pragma unroll
        for (int k2 = 0; k2 < 16; ++k2){
            // k1 = r + 16*k2 -> chunk (k2, tile), offset tid
            float2 t = (k2 & 1) ? cmul(v[PERM(k2)], f1) : cmul(v[PERM(k2)], f0);
            g[k2*4096 + tile*256 + tid] = __floats2half2_rn(t.x, t.y);
            if (k2 & 1) f1 = cmul(f1, stp2); else f0 = cmul(f0, stp2);
        }
    }
}

// ----------- Filter pass 2: row FFTs -> spectrum in chunk layout (shfl) -------
template<int SIGN, bool INPERM>
__device__ __forceinline__ void fft256_shfl(float2 v[16], int r){
    fft16m<SIGN, INPERM>(v);
    float s0, c0;
    sincosf((float)SIGN * (2.0f*PI_F/256.0f) * (float)r, &s0, &c0);
    float2 stp  = make_float2(c0, s0);
    float2 stp2 = cmul(stp, stp);
    float2 fe = make_float2(1.f, 0.f), fo = stp;
    float2 w[16];
#pragma unroll
    for (int k1 = 0; k1 < 16; ++k1){
        w[k1] = (k1 & 1) ? cmul(v[pm(PERM(k1), INPERM)], fo)
                         : cmul(v[pm(PERM(k1), INPERM)], fe);
        if (k1 & 1) fo = cmul(fo, stp2); else fe = cmul(fe, stp2);
    }
#pragma unroll
    for (int m = 1; m < 16; m <<= 1){
        const bool flip = (r & m) != 0;
#pragma unroll
        for (int i = 0; i < 16; ++i){
            if (i & m) continue;
            const int j = i | m;
            float2 send = flip ? w[i] : w[j];
            float2 recv;
            recv.x = __shfl_xor_sync(0xffffffffu, send.x, m);
            recv.y = __shfl_xor_sync(0xffffffffu, send.y, m);
            if (flip) w[i] = recv; else w[j] = recv;
        }
    }
    fft16m<SIGN, false>(w);
#pragma unroll
    for (int i = 0; i < 16; ++i) v[i] = w[i];
}

__global__ void __launch_bounds__(256) k_rows_filt(){
    const int tid = threadIdx.x, r = tid & 15;
    const int tile = blockIdx.x;
    pdl_wait();                                  // g_Gf from P1
    float2 v[16];
#pragma unroll
    for (int i = 0; i < 16; ++i)
        v[i] = g_Gf[tile*4096 + i*256 + tid];
    fft256_shfl<-1,false>(v, r);
#pragma unroll
    for (int k2 = 0; k2 < 16; ++k2)
        g_Wp[tile*4096 + k2*256 + tid] = v[PERM(k2)];
}

// ------ Pass 2: finish forward, multiply W, start inverse (in place) ----------
__global__ void __launch_bounds__(256, 4) k_rows_conv(){
    __shared__ float2 buf[4352];
    const int tid = threadIdx.x, col = tid >> 4, r = tid & 15;   // swapped roles
    const int tile = blockIdx.x;
    __half2* g = g_Gh + (size_t)blockIdx.y * NFFT;
    pdl_wait();                                  // predecessor writes (g_Wp / g_Gh)
    float2 v[16];
#pragma unroll
    for (int i = 0; i < 16; ++i)
        v[i] = __half22float2(g[tile*4096 + i*256 + tid]);  // row tile*16+col
    fft256_reg<-1,false,true,false>(v, buf, col, r);  // Z[row][r+16k2] in v[PERM(k2)]
    // multiply by W in place; logical inverse-input slot k2 lives at v[PERM(k2)]
#pragma unroll
    for (int k2 = 0; k2 < 16; ++k2){
        float2 w = g_Wp[tile*4096 + k2*256 + tid];
        v[PERM(k2)] = cmul(v[PERM(k2)], w);
    }
    fft256_reg<1,true,true,true>(v, buf, col, r);     // D[jj=r+16b] in v[PERM(b)]
    // inverse outer twiddle exp(+2pi i*k1row*jj/65536) with 1/N folded in
    const int k1row = tile*16 + col;
    const float sc = 1.0f / (float)NFFT;
    float s0,c0,s1,c1;
    sincosf((2.0f*PI_F/65536.0f)*(float)(k1row*r),  &s0,&c0);
    sincosf((2.0f*PI_F/65536.0f)*(float)(k1row*32), &s1,&c1);
    float2 f0 = make_float2(c0*sc, s0*sc), stp2 = make_float2(c1,s1);
    sincosf((2.0f*PI_F/65536.0f)*(float)(k1row*16), &s1,&c1);
    float2 f1 = cmul(f0, make_float2(c1,s1));
#pragma unroll
    for (int b = 0; b < 16; ++b){
        float2 t = (b & 1) ? cmul(v[PERM(b)], f1) : cmul(v[PERM(b)], f0);
        g[tile*4096 + b*256 + tid] = __floats2half2_rn(t.x, t.y);
        if (b & 1) f1 = cmul(f1, stp2); else f0 = cmul(f0, stp2);
    }
}

// ---------------- Pass 3: inverse column FFTs + output ------------------------
__global__ void __launch_bounds__(256, 5) k_inv_cols(float* __restrict__ y){
    __shared__ float2 buf[4352];
    const int tid = threadIdx.x, col = tid & 15, r = tid >> 4;
    const int tile = blockIdx.x, pr = blockIdx.y;
    const int j1 = tile*16 + col;
    const __half2* g = g_Gh + (size_t)pr * NFFT;
    pdl_wait();                                  // P2's g writes
    float2 v[16];
#pragma unroll
    for (int n1 = 0; n1 < 16; ++n1)
        v[n1] = __half22float2(g[n1*4096 + tile*256 + tid]);
    fft256_reg<1,false,false,false>(v, buf, col, r);
    float* y0 = y + (size_t)(2*pr)*T_LEN;
    float* y1 = y0 + T_LEN;
#pragma unroll
    for (int k2 = 0; k2 < 8; ++k2){             // j2o = r+16*k2 < 128 only
        int j2o = r + 16*k2;
        float2 t = v[PERM(k2)];                 // 1/N already applied in P2
        int j = j2o*256 + j1;
        __stcs(y0 + j, t.x);
        __stcs(y1 + j, t.y);
    }
}

extern "C" void kernel_launch(void* const* d_in, const int* in_sizes, int n_in,
                              void* d_out, int out_size) {
    const float* x   = (const float*)d_in[0];
    const float* flt = (const float*)d_in[1];
    float* y = (float*)d_out;
    int B = in_sizes[0] / T_LEN;     // 256
    int npairs = B / 2;              // 128

    cudaLaunchAttribute at;
    at.id = cudaLaunchAttributeProgrammaticStreamSerialization;
    at.val.programmaticStreamSerializationAllowed = 1;

    cudaLaunchConfig_t cfg;
    memset(&cfg, 0, sizeof(cfg));
    cfg.blockDim = dim3(256, 1, 1);
    cfg.stream = 0;

    // P1 (full width + filter row) — no PDL attr (first in chain)
    cfg.gridDim = dim3(16, npairs + 1, 1);
    cfg.attrs = nullptr; cfg.numAttrs = 0;
    cudaLaunchKernelEx(&cfg, k_fwd_cols, x, flt);

    cfg.attrs = &at; cfg.numAttrs = 1;

    cfg.gridDim = dim3(16, 1, 1);
    cudaLaunchKernelEx(&cfg, k_rows_filt);

    cfg.gridDim = dim3(16, npairs, 1);
    cudaLaunchKernelEx(&cfg, k_rows_conv);

    cfg.gridDim = dim3(16, npairs, 1);
    cudaLaunchKernelEx(&cfg, k_inv_cols, y);
}